// round 15
// baseline (speedup 1.0000x reference)
#include <cuda_runtime.h>
#include <cuda_fp16.h>

#define SLOPE 0.2f
#define NRB   576                  // node row: A[P1|P3 interleaved,256B] | B[P2|P3,256B] | a1,a2 | pad
#define MAXN  100352
#define MAXE  1000192
#define MAXNB (MAXE / 64)

__device__ float4   g_node[(size_t)MAXN * (NRB / 16)];   // 58MB, 576B/node
__device__ float    g_partM[64 * MAXNB];
__device__ float    g_partS[64 * MAXNB];
__device__ float    g_factB[(size_t)MAXNB * 64];
__device__ unsigned g_scr[(size_t)MAXE * 32];            // fp16 u*exp scratch, 128MB
__device__ unsigned g_W2h[4096];    // k_edge weights fp16, fragment-major [ph][ng][kk(4)][lane][8]
__device__ unsigned g_Wnf[16384];   // k_node weights tf32, fragment-major [ng(4)][kk(8)][lane(32)][16]
__device__ float    g_Wa3[64];
__device__ float    g_cvec[64];
__device__ float    g_Mg[64];
__device__ float    g_invS[64];
__device__ float    g_battn;
__device__ int      g_idx64;

__device__ __forceinline__ float lrelu_f(float x) { return x >= 0.f ? x : SLOPE * x; }
__device__ __forceinline__ unsigned f2tf32(float f) {
    unsigned u; asm("cvt.rna.tf32.f32 %0, %1;" : "=r"(u) : "f"(f)); return u;
}
__device__ __forceinline__ void mma_tf32(float* c, unsigned a0, unsigned a1, unsigned a2, unsigned a3,
                                         unsigned b0, unsigned b1) {
    asm volatile("mma.sync.aligned.m16n8k8.row.col.f32.tf32.tf32.f32 "
                 "{%0,%1,%2,%3}, {%4,%5,%6,%7}, {%8,%9}, {%0,%1,%2,%3};"
                 : "+f"(c[0]), "+f"(c[1]), "+f"(c[2]), "+f"(c[3])
                 : "r"(a0), "r"(a1), "r"(a2), "r"(a3), "r"(b0), "r"(b1));
}
__device__ __forceinline__ void mma_f16(float* c, unsigned a0, unsigned a1, unsigned a2, unsigned a3,
                                        unsigned b0, unsigned b1) {
    asm volatile("mma.sync.aligned.m16n8k16.row.col.f32.f16.f16.f32 "
                 "{%0,%1,%2,%3}, {%4,%5,%6,%7}, {%8,%9}, {%0,%1,%2,%3};"
                 : "+f"(c[0]), "+f"(c[1]), "+f"(c[2]), "+f"(c[3])
                 : "r"(a0), "r"(a1), "r"(a2), "r"(a3), "r"(b0), "r"(b1));
}

__device__ __forceinline__ float wn_val(int k, int col,
                                        const float* W_upd, const float* W_node, const float* W_attn)
{
    if (col < 64)   return W_upd[k * 64 + col];
    if (col < 128)  return W_upd[(64 + k) * 64 + (col - 64)];
    if (col < 192)  return W_node[k * 64 + (col - 128)];
    if (col == 192) return W_attn[k];
    if (col == 193) return W_attn[64 + k];
    return 0.f;
}

__global__ void k_prep(const float* __restrict__ W_attn, const float* __restrict__ b_attn,
                       const float* __restrict__ W_upd,  const float* __restrict__ b_upd,
                       const float* __restrict__ W_edge, const float* __restrict__ b_edge,
                       const float* __restrict__ W_node, const float* __restrict__ b_node,
                       const unsigned* __restrict__ eidx_raw)
{
    int t = threadIdx.x;
    for (int idx = t; idx < 4096; idx += 256) {
        int r    = idx & 7;
        int lane = (idx >> 3) & 31;
        int kk   = (idx >> 8) & 3;
        int ng   = (idx >> 10) & 1;
        int ph   = (idx >> 11) & 1;
        int g = lane >> 2, q = lane & 3;
        int nt = r >> 1, hb = r & 1;
        int kb = kk * 16 + 2 * q + hb * 8;
        int c  = ng * 32 + nt * 8 + g;
        float v0 = (ph == 0) ? W_upd[(128 + kb) * 64 + c]     : W_edge[kb * 64 + c];
        float v1 = (ph == 0) ? W_upd[(128 + kb + 1) * 64 + c] : W_edge[(kb + 1) * 64 + c];
        __half2 h = __floats2half2_rn(v0, v1);
        g_W2h[idx] = *(unsigned*)&h;
    }
    for (int idx = t; idx < 16384; idx += 256) {
        int j    = idx & 15;
        int lane = (idx >> 4) & 31;
        int kk   = (idx >> 9) & 7;
        int ng   = (idx >> 12) & 3;
        float v = 0.f;
        if (j < 14) {
            int g = lane >> 2, q = lane & 3;
            int nt = j >> 1, b = j & 1;
            int k = kk * 8 + q + b * 4;
            int col = ng * 56 + nt * 8 + g;
            v = wn_val(k, col, W_upd, W_node, W_attn);
        }
        g_Wnf[idx] = f2tf32(v);
    }
    if (t < 64) {
        g_cvec[t] = b_edge[t] + 2.f * b_node[t];
        g_Wa3[t]  = W_attn[128 + t];
    }
    if (t == 0) {
        g_battn = b_attn[0];
        int is64 = 1;
        for (int i = 0; i < 32; i++)
            if (eidx_raw[2 * i + 1] != 0u) { is64 = 0; break; }
        g_idx64 = is64;
    }
}

// tf32 MMA node precompute: 32 nodes/block, 194 used cols, K=64
__global__ __launch_bounds__(256) void k_node(const float* __restrict__ ne, int N)
{
    __shared__ unsigned sX[32 * 68];
    __shared__ float    sOut[32 * 228];
    int t = threadIdx.x;
    int n0 = blockIdx.x * 32;

    for (int i = t; i < 32 * 64; i += 256) {
        int n = n0 + (i >> 6);
        float v = (n < N) ? ne[(size_t)n * 64 + (i & 63)] : 0.f;
        sX[(i >> 6) * 68 + (i & 63)] = f2tf32(v);
    }
    __syncthreads();

    int lane = t & 31, warp = t >> 5;
    int m0 = (warp & 1) * 16;
    int ng = warp >> 1;
    int n0c = ng * 56;
    int g = lane >> 2, q = lane & 3;
    const uint4* W4 = (const uint4*)g_Wnf;
    const uint2* W2 = (const uint2*)g_Wnf;

    float acc[7][4];
    #pragma unroll
    for (int nt = 0; nt < 7; nt++)
        #pragma unroll
        for (int j = 0; j < 4; j++) acc[nt][j] = 0.f;

    #pragma unroll
    for (int kk = 0; kk < 8; kk++) {
        unsigned a0 = sX[(m0 + g)     * 68 + kk * 8 + q];
        unsigned a1 = sX[(m0 + g + 8) * 68 + kk * 8 + q];
        unsigned a2 = sX[(m0 + g)     * 68 + kk * 8 + q + 4];
        unsigned a3 = sX[(m0 + g + 8) * 68 + kk * 8 + q + 4];
        int base = ((ng * 8 + kk) * 32 + lane);
        uint4 w0 = __ldg(&W4[base * 4]);
        uint4 w1 = __ldg(&W4[base * 4 + 1]);
        uint4 w2 = __ldg(&W4[base * 4 + 2]);
        uint2 w3 = __ldg(&W2[base * 8 + 6]);
        mma_tf32(acc[0], a0, a1, a2, a3, w0.x, w0.y);
        mma_tf32(acc[1], a0, a1, a2, a3, w0.z, w0.w);
        mma_tf32(acc[2], a0, a1, a2, a3, w1.x, w1.y);
        mma_tf32(acc[3], a0, a1, a2, a3, w1.z, w1.w);
        mma_tf32(acc[4], a0, a1, a2, a3, w2.x, w2.y);
        mma_tf32(acc[5], a0, a1, a2, a3, w2.z, w2.w);
        mma_tf32(acc[6], a0, a1, a2, a3, w3.x, w3.y);
    }
    #pragma unroll
    for (int nt = 0; nt < 7; nt++) {
        int col = n0c + nt * 8 + q * 2;
        sOut[(m0 + g)     * 228 + col]     = acc[nt][0];
        sOut[(m0 + g)     * 228 + col + 1] = acc[nt][1];
        sOut[(m0 + g + 8) * 228 + col]     = acc[nt][2];
        sOut[(m0 + g + 8) * 228 + col + 1] = acc[nt][3];
    }
    __syncthreads();

    // pack interleaved fp16 node table: A[j*8]={P1,P3}, B[256+j*8]={P2,P3}
    for (int i = t; i < 32 * 32; i += 256) {
        int n = i >> 5, j = i & 31;
        if (n0 + n >= N) continue;
        char* dst = (char*)g_node + (size_t)(n0 + n) * NRB;
        __half2 p1 = __floats2half2_rn(sOut[n * 228 + 2 * j],       sOut[n * 228 + 2 * j + 1]);
        __half2 p2 = __floats2half2_rn(sOut[n * 228 + 64 + 2 * j],  sOut[n * 228 + 65 + 2 * j]);
        __half2 p3 = __floats2half2_rn(sOut[n * 228 + 128 + 2 * j], sOut[n * 228 + 129 + 2 * j]);
        uint2 ra = make_uint2(*(unsigned*)&p1, *(unsigned*)&p3);
        uint2 rb = make_uint2(*(unsigned*)&p2, *(unsigned*)&p3);
        *(uint2*)(dst + j * 8)       = ra;
        *(uint2*)(dst + 256 + j * 8) = rb;
    }
    if (t < 32 && n0 + t < N) {
        char* dst = (char*)g_node + (size_t)(n0 + t) * NRB;
        *(float*)(dst + 512) = sOut[t * 228 + 192];
        *(float*)(dst + 516) = sOut[t * 228 + 193];
    }
}

// dummy kernel — keeps k_edge in the fixed ncu capture slot
__global__ void k_mark() { if (threadIdx.x < 64) g_Mg[threadIdx.x] = 0.f; }

// smem (u32): sAh[64*36] fp16 tile | sRes[64*68] | sUf[64*64] | sPM[8*68] | sPS[8*68] | misc
#define SAH_U (64 * 36)
#define SR_F  (64 * 68)
#define SUF_F (64 * 64)
#define SP_F  (8 * 68)
#define SMEM_F (SAH_U + SR_F + SUF_F + 2 * SP_F + 256)
#define SMEM_BYTES (SMEM_F * 4)

__global__ __launch_bounds__(256, 4) void k_edge(const float* __restrict__ eemb,
                                                 const void*  __restrict__ eidx,
                                                 const float* __restrict__ bupd,
                                                 int E)
{
    extern __shared__ float smem[];
    unsigned* sAh   = (unsigned*)smem;       // fp16: edge tile → updated
    float*    sRes  = smem + SAH_U;          // E3 → P3sum → P3sum+T
    float*    sUf   = smem + SAH_U + SR_F;   // updated fp32 (pitch 64)
    float*    sPM   = smem + SAH_U + SR_F + SUF_F;
    float*    sPS   = sPM + SP_F;
    float*    sWa   = sPS + SP_F;
    float*    sGate = sWa + 64;
    int*      sSrc  = (int*)(sGate + 64);    // byte offsets into g_node
    int*      sDst  = sSrc + 64;

    int t = threadIdx.x;
    int e0g = blockIdx.x * 64;
    int idx64 = g_idx64;

    if (t < 128) {
        int j = t & 63;
        int ee = min(e0g + j, E - 1);
        size_t pos = (t < 64) ? (size_t)ee : (size_t)E + (size_t)ee;
        int v = idx64 ? (int)((const long long*)eidx)[pos] : ((const int*)eidx)[pos];
        if (t < 64) sSrc[j] = v * NRB; else sDst[j] = v * NRB;
    }
    if (t >= 128 && t < 192) sWa[t - 128] = g_Wa3[t - 128];
    for (int i = t; i < 64 * 32; i += 256) {
        int e = i >> 5, k2 = i & 31;
        int ee = min(e0g + e, E - 1);
        float2 v = __ldcs((const float2*)(eemb + (size_t)ee * 64 + k2 * 2));
        __half2 h = __floats2half2_rn(v.x, v.y);
        sAh[e * 36 + k2] = *(unsigned*)&h;
    }
    __syncthreads();

    int lane = t & 31, warp = t >> 5;
    int m0 = (warp & 3) * 16;
    int ng = warp >> 2;
    int n0 = ng * 32;
    int g = lane >> 2, q = lane & 3;
    const uint4* Wh = (const uint4*)g_W2h;    // 1024 uint4; phase1 starts at 512
    const char* nb = (const char*)g_node;

    int c = lane * 2;
    int cb = lane * 8;               // uint2 byte offset within region
    int ebase = warp * 8;

    // ---- prefetch gathers for edges ebase..ebase+3 (overlap with MMA1) ----
    uint2 S1[4], D1[4];
    #pragma unroll
    for (int i = 0; i < 4; i++) {
        int e = ebase + i;
        S1[i] = *(const uint2*)(nb + sSrc[e] + cb);          // {P1, P3s}
        D1[i] = *(const uint2*)(nb + sDst[e] + 256 + cb);    // {P2, P3d}
    }

    // ---- MMA1 (fp16, K=16/step): E3 = A @ Wu3 ----
    float acc[4][4];
    #pragma unroll
    for (int nt = 0; nt < 4; nt++)
        #pragma unroll
        for (int j = 0; j < 4; j++) acc[nt][j] = 0.f;
    #pragma unroll
    for (int kk = 0; kk < 4; kk++) {
        unsigned a0 = sAh[(m0 + g)     * 36 + kk * 8 + q];
        unsigned a1 = sAh[(m0 + g + 8) * 36 + kk * 8 + q];
        unsigned a2 = sAh[(m0 + g)     * 36 + kk * 8 + q + 4];
        unsigned a3 = sAh[(m0 + g + 8) * 36 + kk * 8 + q + 4];
        int b8 = (ng * 4 + kk) * 64 + lane * 2;
        uint4 w0 = __ldg(&Wh[b8]);
        uint4 w1 = __ldg(&Wh[b8 + 1]);
        mma_f16(acc[0], a0, a1, a2, a3, w0.x, w0.y);
        mma_f16(acc[1], a0, a1, a2, a3, w0.z, w0.w);
        mma_f16(acc[2], a0, a1, a2, a3, w1.x, w1.y);
        mma_f16(acc[3], a0, a1, a2, a3, w1.z, w1.w);
    }
    #pragma unroll
    for (int nt = 0; nt < 4; nt++) {
        int col = n0 + nt * 8 + q * 2;
        sRes[(m0 + g)     * 68 + col]     = acc[nt][0];
        sRes[(m0 + g)     * 68 + col + 1] = acc[nt][1];
        sRes[(m0 + g + 8) * 68 + col]     = acc[nt][2];
        sRes[(m0 + g + 8) * 68 + col + 1] = acc[nt][3];
    }
    // gate (reads fp16 edge tile)
    if (t < 64) {
        float s = 0.f;
        #pragma unroll 8
        for (int k2 = 0; k2 < 32; k2++) {
            unsigned hb = sAh[t * 36 + k2];
            float2 a = __half22float2(*(__half2*)&hb);
            s += a.x * sWa[2 * k2] + a.y * sWa[2 * k2 + 1];
        }
        float a1v = *(const float*)(nb + sSrc[t] + 512);
        float a2v = *(const float*)(nb + sDst[t] + 516);
        sGate[t] = 1.f / (1.f + __expf(-lrelu_f(a1v + a2v + s + g_battn)));
    }
    __syncthreads();

    // ---- Phase B1: prefetched batch + pipelined second batch ----
    float2 bu2 = make_float2(bupd[c], bupd[c + 1]);
    float2 cv2 = make_float2(g_cvec[c], g_cvec[c + 1]);

    uint2 S2[4], D2[4];
    #pragma unroll
    for (int i = 0; i < 4; i++) {
        int e = ebase + 4 + i;
        S2[i] = *(const uint2*)(nb + sSrc[e] + cb);
        D2[i] = *(const uint2*)(nb + sDst[e] + 256 + cb);
    }
    #pragma unroll
    for (int i = 0; i < 4; i++) {
        int e = ebase + i;
        float gt = sGate[e];
        float2 p1  = __half22float2(*(__half2*)&S1[i].x);
        float2 p3a = __half22float2(*(__half2*)&S1[i].y);
        float2 p2  = __half22float2(*(__half2*)&D1[i].x);
        float2 p3b = __half22float2(*(__half2*)&D1[i].y);
        float2 e3 = *(const float2*)&sRes[e * 68 + c];
        float2 u;
        u.x = gt * (p1.x + p2.x + e3.x + bu2.x);
        u.y = gt * (p1.y + p2.y + e3.y + bu2.y);
        *(float2*)&sUf[e * 64 + c] = u;
        __half2 uh = __floats2half2_rn(u.x, u.y);
        sAh[e * 36 + lane] = *(unsigned*)&uh;
        *(float2*)&sRes[e * 68 + c] = make_float2(p3a.x + p3b.x, p3a.y + p3b.y);
    }
    #pragma unroll
    for (int i = 0; i < 4; i++) {
        int e = ebase + 4 + i;
        float gt = sGate[e];
        float2 p1  = __half22float2(*(__half2*)&S2[i].x);
        float2 p3a = __half22float2(*(__half2*)&S2[i].y);
        float2 p2  = __half22float2(*(__half2*)&D2[i].x);
        float2 p3b = __half22float2(*(__half2*)&D2[i].y);
        float2 e3 = *(const float2*)&sRes[e * 68 + c];
        float2 u;
        u.x = gt * (p1.x + p2.x + e3.x + bu2.x);
        u.y = gt * (p1.y + p2.y + e3.y + bu2.y);
        *(float2*)&sUf[e * 64 + c] = u;
        __half2 uh = __floats2half2_rn(u.x, u.y);
        sAh[e * 36 + lane] = *(unsigned*)&uh;
        *(float2*)&sRes[e * 68 + c] = make_float2(p3a.x + p3b.x, p3a.y + p3b.y);
    }
    __syncthreads();

    // ---- MMA2 (fp16): T = updated @ W_edge; accumulate T into sRes (P3sum) ----
    #pragma unroll
    for (int nt = 0; nt < 4; nt++)
        #pragma unroll
        for (int j = 0; j < 4; j++) acc[nt][j] = 0.f;
    #pragma unroll
    for (int kk = 0; kk < 4; kk++) {
        unsigned a0 = sAh[(m0 + g)     * 36 + kk * 8 + q];
        unsigned a1 = sAh[(m0 + g + 8) * 36 + kk * 8 + q];
        unsigned a2 = sAh[(m0 + g)     * 36 + kk * 8 + q + 4];
        unsigned a3 = sAh[(m0 + g + 8) * 36 + kk * 8 + q + 4];
        int b8 = 512 + (ng * 4 + kk) * 64 + lane * 2;
        uint4 w0 = __ldg(&Wh[b8]);
        uint4 w1 = __ldg(&Wh[b8 + 1]);
        mma_f16(acc[0], a0, a1, a2, a3, w0.x, w0.y);
        mma_f16(acc[1], a0, a1, a2, a3, w0.z, w0.w);
        mma_f16(acc[2], a0, a1, a2, a3, w1.x, w1.y);
        mma_f16(acc[3], a0, a1, a2, a3, w1.z, w1.w);
    }
    #pragma unroll
    for (int nt = 0; nt < 4; nt++) {
        int col = n0 + nt * 8 + q * 2;
        sRes[(m0 + g)     * 68 + col]     += acc[nt][0];
        sRes[(m0 + g)     * 68 + col + 1] += acc[nt][1];
        sRes[(m0 + g + 8) * 68 + col]     += acc[nt][2];
        sRes[(m0 + g + 8) * 68 + col + 1] += acc[nt][3];
    }
    __syncthreads();

    // ---- Phase B2: z = lrelu(sRes + cvec); softmax; store fp16 scratch ----
    float2 zs[8];
    #pragma unroll
    for (int i = 0; i < 8; i++) {
        int e = ebase + i;
        bool v = (e0g + e) < E;
        float2 tv = *(const float2*)&sRes[e * 68 + c];
        float zx = lrelu_f(tv.x + cv2.x);
        float zy = lrelu_f(tv.y + cv2.y);
        zs[i] = v ? make_float2(zx, zy) : make_float2(-1e30f, -1e30f);
    }
    float2 ml = make_float2(-1e30f, -1e30f);
    #pragma unroll
    for (int i = 0; i < 8; i++) {
        ml.x = fmaxf(ml.x, zs[i].x);
        ml.y = fmaxf(ml.y, zs[i].y);
    }
    *(float2*)&sPM[warp * 68 + c] = ml;
    __syncthreads();
    float2 mb = make_float2(-1e30f, -1e30f);
    #pragma unroll
    for (int w2 = 0; w2 < 8; w2++) {
        mb.x = fmaxf(mb.x, sPM[w2 * 68 + c]);
        mb.y = fmaxf(mb.y, sPM[w2 * 68 + c + 1]);
    }
    float2 sl = make_float2(0.f, 0.f);
    #pragma unroll
    for (int i = 0; i < 8; i++) {
        int e = ebase + i;
        if ((e0g + e) < E) {
            float ex = __expf(zs[i].x - mb.x);
            float ey = __expf(zs[i].y - mb.y);
            sl.x += ex; sl.y += ey;
            float2 u = *(const float2*)&sUf[e * 64 + c];
            __half2 oh = __floats2half2_rn(u.x * ex, u.y * ey);
            __stcs(&g_scr[(size_t)(e0g + e) * 32 + lane], *(unsigned*)&oh);
        }
    }
    *(float2*)&sPS[warp * 68 + c] = sl;
    __syncthreads();
    if (warp == 0) {
        float sx = 0.f, sy = 0.f;
        #pragma unroll
        for (int w2 = 0; w2 < 8; w2++) {
            sx += sPS[w2 * 68 + c];
            sy += sPS[w2 * 68 + c + 1];
        }
        g_partM[c * MAXNB + blockIdx.x]       = mb.x;
        g_partM[(c + 1) * MAXNB + blockIdx.x] = mb.y;
        g_partS[c * MAXNB + blockIdx.x]       = sx;
        g_partS[(c + 1) * MAXNB + blockIdx.x] = sy;
    }
}

__global__ void k_combine(int NB)
{
    int c = blockIdx.x, t = threadIdx.x;
    float m = -1e30f, s = 0.f;
    for (int b = t; b < NB; b += 256) {
        float mb = g_partM[c * MAXNB + b], sb = g_partS[c * MAXNB + b];
        float M2 = fmaxf(m, mb);
        s = s * __expf(m - M2) + sb * __expf(mb - M2);
        m = M2;
    }
    __shared__ float sm[256], ss[256];
    sm[t] = m; ss[t] = s; __syncthreads();
    for (int off = 128; off > 0; off >>= 1) {
        if (t < off) {
            float M2 = fmaxf(sm[t], sm[t + off]);
            ss[t] = ss[t] * __expf(sm[t] - M2) + ss[t + off] * __expf(sm[t + off] - M2);
            sm[t] = M2;
        }
        __syncthreads();
    }
    if (t == 0) { g_Mg[c] = sm[0]; g_invS[c] = 1.f / ss[0]; }
}

__global__ void k_fact(int NB)
{
    int idx = blockIdx.x * 256 + threadIdx.x;
    int b = idx >> 6, c = idx & 63;
    if (b >= NB) return;
    g_factB[(size_t)b * 64 + c] = __expf(g_partM[c * MAXNB + b] - g_Mg[c]) * g_invS[c];
}

// final: out = scratch_fp16 * factor   (read 128MB fp16, write 256MB fp32)
__global__ __launch_bounds__(256) void k_pass2(float2* __restrict__ out, int E)
{
    __shared__ float sf[64];
    int b = blockIdx.x;
    int t = threadIdx.x;
    if (t < 64) sf[t] = g_factB[(size_t)b * 64 + t];
    __syncthreads();
    size_t base = (size_t)b * 2048;
    #pragma unroll
    for (int r = 0; r < 8; r++) {
        size_t i = base + r * 256 + t;
        int e = (int)(i >> 5);
        if (e < E) {
            int c = ((int)i & 31) * 2;
            unsigned s = __ldcs(&g_scr[i]);
            float2 v = __half22float2(*(__half2*)&s);
            __stcs(&out[i], make_float2(v.x * sf[c], v.y * sf[c + 1]));
        }
    }
}

extern "C" void kernel_launch(void* const* d_in, const int* in_sizes, int n_in,
                              void* d_out, int out_size)
{
    const float* eemb = (const float*)d_in[0];
    const float* ne   = (const float*)d_in[2];
    const float* Wa   = (const float*)d_in[3];
    const float* ba   = (const float*)d_in[4];
    const float* Wu   = (const float*)d_in[5];
    const float* bu   = (const float*)d_in[6];
    const float* We   = (const float*)d_in[7];
    const float* be   = (const float*)d_in[8];
    const float* Wn   = (const float*)d_in[9];
    const float* bn   = (const float*)d_in[10];
    const void*  eidx = d_in[11];
    float* out = (float*)d_out;

    int E = in_sizes[0] / 64;
    int N = in_sizes[2] / 64;
    int NB = (E + 63) / 64;

    cudaFuncSetAttribute(k_edge, cudaFuncAttributeMaxDynamicSharedMemorySize, SMEM_BYTES);

    k_prep<<<1, 256>>>(Wa, ba, Wu, bu, We, be, Wn, bn, (const unsigned*)eidx);
    k_node<<<(N + 31) / 32, 256>>>(ne, N);
    k_mark<<<1, 64>>>();
    k_edge<<<NB, 256, SMEM_BYTES>>>(eemb, eidx, bu, E);
    k_combine<<<64, 256>>>(NB);
    k_fact<<<(NB * 64 + 255) / 256, 256>>>(NB);
    k_pass2<<<NB, 256>>>((float2*)out, E);
}

// round 16
// speedup vs baseline: 1.1088x; 1.1088x over previous
#include <cuda_runtime.h>
#include <cuda_fp16.h>

#define SLOPE 0.2f
#define NRB   576                  // node row: A[P1|P3 interleaved,256B] | B[P2|P3,256B] | a1,a2 | pad
#define MAXN  100352
#define MAXE  1000192
#define MAXNB (MAXE / 64)

__device__ float4   g_node[(size_t)MAXN * (NRB / 16)];   // 58MB, 576B/node
__device__ float    g_partM[64 * MAXNB];
__device__ float    g_partS[64 * MAXNB];
__device__ float    g_factB[(size_t)MAXNB * 64];
__device__ unsigned g_scr[(size_t)MAXE * 32];            // fp16 u*exp scratch, 128MB
__device__ unsigned g_W2h[4096];    // k_edge weights fp16, fragment-major [ph][ng][kk(4)][lane][8]
__device__ unsigned g_Wnf[16384];   // k_node weights tf32, fragment-major [ng(4)][kk(8)][lane(32)][16]
__device__ float    g_Wa3[64];
__device__ float    g_cvec[64];
__device__ float    g_Mg[64];
__device__ float    g_invS[64];
__device__ float    g_battn;
__device__ int      g_idx64;

__device__ __forceinline__ float lrelu_f(float x) { return x >= 0.f ? x : SLOPE * x; }
__device__ __forceinline__ unsigned f2tf32(float f) {
    unsigned u; asm("cvt.rna.tf32.f32 %0, %1;" : "=r"(u) : "f"(f)); return u;
}
__device__ __forceinline__ void mma_tf32(float* c, unsigned a0, unsigned a1, unsigned a2, unsigned a3,
                                         unsigned b0, unsigned b1) {
    asm volatile("mma.sync.aligned.m16n8k8.row.col.f32.tf32.tf32.f32 "
                 "{%0,%1,%2,%3}, {%4,%5,%6,%7}, {%8,%9}, {%0,%1,%2,%3};"
                 : "+f"(c[0]), "+f"(c[1]), "+f"(c[2]), "+f"(c[3])
                 : "r"(a0), "r"(a1), "r"(a2), "r"(a3), "r"(b0), "r"(b1));
}
__device__ __forceinline__ void mma_f16(float* c, unsigned a0, unsigned a1, unsigned a2, unsigned a3,
                                        unsigned b0, unsigned b1) {
    asm volatile("mma.sync.aligned.m16n8k16.row.col.f32.f16.f16.f32 "
                 "{%0,%1,%2,%3}, {%4,%5,%6,%7}, {%8,%9}, {%0,%1,%2,%3};"
                 : "+f"(c[0]), "+f"(c[1]), "+f"(c[2]), "+f"(c[3])
                 : "r"(a0), "r"(a1), "r"(a2), "r"(a3), "r"(b0), "r"(b1));
}

__device__ __forceinline__ float wn_val(int k, int col,
                                        const float* W_upd, const float* W_node, const float* W_attn)
{
    if (col < 64)   return W_upd[k * 64 + col];
    if (col < 128)  return W_upd[(64 + k) * 64 + (col - 64)];
    if (col < 192)  return W_node[k * 64 + (col - 128)];
    if (col == 192) return W_attn[k];
    if (col == 193) return W_attn[64 + k];
    return 0.f;
}

// parallel prep: flat space [0,4096) W2h | [4096,20480) Wnf | [20480,20544) vec | 20544 scalars
__global__ void k_prep(const float* __restrict__ W_attn, const float* __restrict__ b_attn,
                       const float* __restrict__ W_upd,  const float* __restrict__ b_upd,
                       const float* __restrict__ W_edge, const float* __restrict__ b_edge,
                       const float* __restrict__ W_node, const float* __restrict__ b_node,
                       const unsigned* __restrict__ eidx_raw)
{
    int gid = blockIdx.x * 256 + threadIdx.x;
    if (gid < 4096) {
        int idx = gid;
        int r    = idx & 7;
        int lane = (idx >> 3) & 31;
        int kk   = (idx >> 8) & 3;
        int ng   = (idx >> 10) & 1;
        int ph   = (idx >> 11) & 1;
        int g = lane >> 2, q = lane & 3;
        int nt = r >> 1, hb = r & 1;
        int kb = kk * 16 + 2 * q + hb * 8;
        int c  = ng * 32 + nt * 8 + g;
        float v0 = (ph == 0) ? W_upd[(128 + kb) * 64 + c]     : W_edge[kb * 64 + c];
        float v1 = (ph == 0) ? W_upd[(128 + kb + 1) * 64 + c] : W_edge[(kb + 1) * 64 + c];
        __half2 h = __floats2half2_rn(v0, v1);
        g_W2h[idx] = *(unsigned*)&h;
    } else if (gid < 20480) {
        int idx = gid - 4096;
        int j    = idx & 15;
        int lane = (idx >> 4) & 31;
        int kk   = (idx >> 9) & 7;
        int ng   = (idx >> 12) & 3;
        float v = 0.f;
        if (j < 14) {
            int g = lane >> 2, q = lane & 3;
            int nt = j >> 1, b = j & 1;
            int k = kk * 8 + q + b * 4;
            int col = ng * 56 + nt * 8 + g;
            v = wn_val(k, col, W_upd, W_node, W_attn);
        }
        g_Wnf[idx] = f2tf32(v);
    } else if (gid < 20544) {
        int t = gid - 20480;
        g_cvec[t] = b_edge[t] + 2.f * b_node[t];
        g_Wa3[t]  = W_attn[128 + t];
    } else if (gid == 20544) {
        g_battn = b_attn[0];
        int is64 = 1;
        for (int i = 0; i < 32; i++)
            if (eidx_raw[2 * i + 1] != 0u) { is64 = 0; break; }
        g_idx64 = is64;
    }
}

// tf32 MMA node precompute: 32 nodes/block, 194 used cols, K=64
__global__ __launch_bounds__(256) void k_node(const float* __restrict__ ne, int N)
{
    __shared__ unsigned sX[32 * 68];
    __shared__ float    sOut[32 * 228];
    int t = threadIdx.x;
    int n0 = blockIdx.x * 32;

    for (int i = t; i < 32 * 64; i += 256) {
        int n = n0 + (i >> 6);
        float v = (n < N) ? ne[(size_t)n * 64 + (i & 63)] : 0.f;
        sX[(i >> 6) * 68 + (i & 63)] = f2tf32(v);
    }
    __syncthreads();

    int lane = t & 31, warp = t >> 5;
    int m0 = (warp & 1) * 16;
    int ng = warp >> 1;
    int n0c = ng * 56;
    int g = lane >> 2, q = lane & 3;
    const uint4* W4 = (const uint4*)g_Wnf;
    const uint2* W2 = (const uint2*)g_Wnf;

    float acc[7][4];
    #pragma unroll
    for (int nt = 0; nt < 7; nt++)
        #pragma unroll
        for (int j = 0; j < 4; j++) acc[nt][j] = 0.f;

    #pragma unroll
    for (int kk = 0; kk < 8; kk++) {
        unsigned a0 = sX[(m0 + g)     * 68 + kk * 8 + q];
        unsigned a1 = sX[(m0 + g + 8) * 68 + kk * 8 + q];
        unsigned a2 = sX[(m0 + g)     * 68 + kk * 8 + q + 4];
        unsigned a3 = sX[(m0 + g + 8) * 68 + kk * 8 + q + 4];
        int base = ((ng * 8 + kk) * 32 + lane);
        uint4 w0 = __ldg(&W4[base * 4]);
        uint4 w1 = __ldg(&W4[base * 4 + 1]);
        uint4 w2 = __ldg(&W4[base * 4 + 2]);
        uint2 w3 = __ldg(&W2[base * 8 + 6]);
        mma_tf32(acc[0], a0, a1, a2, a3, w0.x, w0.y);
        mma_tf32(acc[1], a0, a1, a2, a3, w0.z, w0.w);
        mma_tf32(acc[2], a0, a1, a2, a3, w1.x, w1.y);
        mma_tf32(acc[3], a0, a1, a2, a3, w1.z, w1.w);
        mma_tf32(acc[4], a0, a1, a2, a3, w2.x, w2.y);
        mma_tf32(acc[5], a0, a1, a2, a3, w2.z, w2.w);
        mma_tf32(acc[6], a0, a1, a2, a3, w3.x, w3.y);
    }
    #pragma unroll
    for (int nt = 0; nt < 7; nt++) {
        int col = n0c + nt * 8 + q * 2;
        sOut[(m0 + g)     * 228 + col]     = acc[nt][0];
        sOut[(m0 + g)     * 228 + col + 1] = acc[nt][1];
        sOut[(m0 + g + 8) * 228 + col]     = acc[nt][2];
        sOut[(m0 + g + 8) * 228 + col + 1] = acc[nt][3];
    }
    __syncthreads();

    // pack interleaved fp16 node table: A[j*8]={P1,P3}, B[256+j*8]={P2,P3}
    for (int i = t; i < 32 * 32; i += 256) {
        int n = i >> 5, j = i & 31;
        if (n0 + n >= N) continue;
        char* dst = (char*)g_node + (size_t)(n0 + n) * NRB;
        __half2 p1 = __floats2half2_rn(sOut[n * 228 + 2 * j],       sOut[n * 228 + 2 * j + 1]);
        __half2 p2 = __floats2half2_rn(sOut[n * 228 + 64 + 2 * j],  sOut[n * 228 + 65 + 2 * j]);
        __half2 p3 = __floats2half2_rn(sOut[n * 228 + 128 + 2 * j], sOut[n * 228 + 129 + 2 * j]);
        uint2 ra = make_uint2(*(unsigned*)&p1, *(unsigned*)&p3);
        uint2 rb = make_uint2(*(unsigned*)&p2, *(unsigned*)&p3);
        *(uint2*)(dst + j * 8)       = ra;
        *(uint2*)(dst + 256 + j * 8) = rb;
    }
    if (t < 32 && n0 + t < N) {
        char* dst = (char*)g_node + (size_t)(n0 + t) * NRB;
        *(float*)(dst + 512) = sOut[t * 228 + 192];
        *(float*)(dst + 516) = sOut[t * 228 + 193];
    }
}

// dummy kernel — keeps k_edge in the fixed ncu capture slot
__global__ void k_mark() { if (threadIdx.x < 64) g_Mg[threadIdx.x] = 0.f; }

// smem (u32): sAh[64*36] fp16 tile | sRes[64*68] | sUf[64*64] | sPM[8*68] | sPS[8*68] | misc
#define SAH_U (64 * 36)
#define SR_F  (64 * 68)
#define SUF_F (64 * 64)
#define SP_F  (8 * 68)
#define SMEM_F (SAH_U + SR_F + SUF_F + 2 * SP_F + 256)
#define SMEM_BYTES (SMEM_F * 4)

__global__ __launch_bounds__(256, 4) void k_edge(const float* __restrict__ eemb,
                                                 const void*  __restrict__ eidx,
                                                 const float* __restrict__ bupd,
                                                 int E)
{
    extern __shared__ float smem[];
    unsigned* sAh   = (unsigned*)smem;       // fp16: edge tile → updated
    float*    sRes  = smem + SAH_U;          // E3 → P3sum → P3sum+T
    float*    sUf   = smem + SAH_U + SR_F;   // updated fp32 (pitch 64)
    float*    sPM   = smem + SAH_U + SR_F + SUF_F;
    float*    sPS   = sPM + SP_F;
    float*    sWa   = sPS + SP_F;
    float*    sGate = sWa + 64;
    int*      sSrc  = (int*)(sGate + 64);    // byte offsets into g_node
    int*      sDst  = sSrc + 64;

    int t = threadIdx.x;
    int e0g = blockIdx.x * 64;
    int idx64 = g_idx64;

    if (t < 128) {
        int j = t & 63;
        int ee = min(e0g + j, E - 1);
        size_t pos = (t < 64) ? (size_t)ee : (size_t)E + (size_t)ee;
        int v = idx64 ? (int)((const long long*)eidx)[pos] : ((const int*)eidx)[pos];
        if (t < 64) sSrc[j] = v * NRB; else sDst[j] = v * NRB;
    }
    if (t >= 128 && t < 192) sWa[t - 128] = g_Wa3[t - 128];
    for (int i = t; i < 64 * 32; i += 256) {
        int e = i >> 5, k2 = i & 31;
        int ee = min(e0g + e, E - 1);
        float2 v = __ldcs((const float2*)(eemb + (size_t)ee * 64 + k2 * 2));
        __half2 h = __floats2half2_rn(v.x, v.y);
        sAh[e * 36 + k2] = *(unsigned*)&h;
    }
    __syncthreads();

    int lane = t & 31, warp = t >> 5;
    int m0 = (warp & 3) * 16;
    int ng = warp >> 2;
    int n0 = ng * 32;
    int g = lane >> 2, q = lane & 3;
    const uint4* Wh = (const uint4*)g_W2h;    // 1024 uint4; phase1 starts at 512
    const char* nb = (const char*)g_node;

    int c = lane * 2;
    int cb = lane * 8;
    int ebase = warp * 8;

    // ---- prefetch gathers for edges ebase..ebase+3 (overlap with MMA1) ----
    uint2 S1[4], D1[4];
    #pragma unroll
    for (int i = 0; i < 4; i++) {
        int e = ebase + i;
        S1[i] = *(const uint2*)(nb + sSrc[e] + cb);          // {P1, P3s}
        D1[i] = *(const uint2*)(nb + sDst[e] + 256 + cb);    // {P2, P3d}
    }

    // ---- MMA1 (fp16, K=16/step): E3 = A @ Wu3 ----
    float acc[4][4];
    #pragma unroll
    for (int nt = 0; nt < 4; nt++)
        #pragma unroll
        for (int j = 0; j < 4; j++) acc[nt][j] = 0.f;
    #pragma unroll
    for (int kk = 0; kk < 4; kk++) {
        unsigned a0 = sAh[(m0 + g)     * 36 + kk * 8 + q];
        unsigned a1 = sAh[(m0 + g + 8) * 36 + kk * 8 + q];
        unsigned a2 = sAh[(m0 + g)     * 36 + kk * 8 + q + 4];
        unsigned a3 = sAh[(m0 + g + 8) * 36 + kk * 8 + q + 4];
        int b8 = (ng * 4 + kk) * 64 + lane * 2;
        uint4 w0 = __ldg(&Wh[b8]);
        uint4 w1 = __ldg(&Wh[b8 + 1]);
        mma_f16(acc[0], a0, a1, a2, a3, w0.x, w0.y);
        mma_f16(acc[1], a0, a1, a2, a3, w0.z, w0.w);
        mma_f16(acc[2], a0, a1, a2, a3, w1.x, w1.y);
        mma_f16(acc[3], a0, a1, a2, a3, w1.z, w1.w);
    }
    #pragma unroll
    for (int nt = 0; nt < 4; nt++) {
        int col = n0 + nt * 8 + q * 2;
        sRes[(m0 + g)     * 68 + col]     = acc[nt][0];
        sRes[(m0 + g)     * 68 + col + 1] = acc[nt][1];
        sRes[(m0 + g + 8) * 68 + col]     = acc[nt][2];
        sRes[(m0 + g + 8) * 68 + col + 1] = acc[nt][3];
    }
    // gate (reads fp16 edge tile)
    if (t < 64) {
        float s = 0.f;
        #pragma unroll 8
        for (int k2 = 0; k2 < 32; k2++) {
            unsigned hb = sAh[t * 36 + k2];
            float2 a = __half22float2(*(__half2*)&hb);
            s += a.x * sWa[2 * k2] + a.y * sWa[2 * k2 + 1];
        }
        float a1v = *(const float*)(nb + sSrc[t] + 512);
        float a2v = *(const float*)(nb + sDst[t] + 516);
        sGate[t] = 1.f / (1.f + __expf(-lrelu_f(a1v + a2v + s + g_battn)));
    }
    __syncthreads();

    // ---- Phase B1: prefetched batch + pipelined second batch ----
    float2 bu2 = make_float2(bupd[c], bupd[c + 1]);
    float2 cv2 = make_float2(g_cvec[c], g_cvec[c + 1]);

    uint2 S2[4], D2[4];
    #pragma unroll
    for (int i = 0; i < 4; i++) {
        int e = ebase + 4 + i;
        S2[i] = *(const uint2*)(nb + sSrc[e] + cb);
        D2[i] = *(const uint2*)(nb + sDst[e] + 256 + cb);
    }
    #pragma unroll
    for (int i = 0; i < 4; i++) {
        int e = ebase + i;
        float gt = sGate[e];
        float2 p1  = __half22float2(*(__half2*)&S1[i].x);
        float2 p3a = __half22float2(*(__half2*)&S1[i].y);
        float2 p2  = __half22float2(*(__half2*)&D1[i].x);
        float2 p3b = __half22float2(*(__half2*)&D1[i].y);
        float2 e3 = *(const float2*)&sRes[e * 68 + c];
        float2 u;
        u.x = gt * (p1.x + p2.x + e3.x + bu2.x);
        u.y = gt * (p1.y + p2.y + e3.y + bu2.y);
        *(float2*)&sUf[e * 64 + c] = u;
        __half2 uh = __floats2half2_rn(u.x, u.y);
        sAh[e * 36 + lane] = *(unsigned*)&uh;
        *(float2*)&sRes[e * 68 + c] = make_float2(p3a.x + p3b.x, p3a.y + p3b.y);
    }
    #pragma unroll
    for (int i = 0; i < 4; i++) {
        int e = ebase + 4 + i;
        float gt = sGate[e];
        float2 p1  = __half22float2(*(__half2*)&S2[i].x);
        float2 p3a = __half22float2(*(__half2*)&S2[i].y);
        float2 p2  = __half22float2(*(__half2*)&D2[i].x);
        float2 p3b = __half22float2(*(__half2*)&D2[i].y);
        float2 e3 = *(const float2*)&sRes[e * 68 + c];
        float2 u;
        u.x = gt * (p1.x + p2.x + e3.x + bu2.x);
        u.y = gt * (p1.y + p2.y + e3.y + bu2.y);
        *(float2*)&sUf[e * 64 + c] = u;
        __half2 uh = __floats2half2_rn(u.x, u.y);
        sAh[e * 36 + lane] = *(unsigned*)&uh;
        *(float2*)&sRes[e * 68 + c] = make_float2(p3a.x + p3b.x, p3a.y + p3b.y);
    }
    __syncthreads();

    // ---- MMA2 (fp16): T = updated @ W_edge; accumulate T into sRes (P3sum) ----
    #pragma unroll
    for (int nt = 0; nt < 4; nt++)
        #pragma unroll
        for (int j = 0; j < 4; j++) acc[nt][j] = 0.f;
    #pragma unroll
    for (int kk = 0; kk < 4; kk++) {
        unsigned a0 = sAh[(m0 + g)     * 36 + kk * 8 + q];
        unsigned a1 = sAh[(m0 + g + 8) * 36 + kk * 8 + q];
        unsigned a2 = sAh[(m0 + g)     * 36 + kk * 8 + q + 4];
        unsigned a3 = sAh[(m0 + g + 8) * 36 + kk * 8 + q + 4];
        int b8 = 512 + (ng * 4 + kk) * 64 + lane * 2;
        uint4 w0 = __ldg(&Wh[b8]);
        uint4 w1 = __ldg(&Wh[b8 + 1]);
        mma_f16(acc[0], a0, a1, a2, a3, w0.x, w0.y);
        mma_f16(acc[1], a0, a1, a2, a3, w0.z, w0.w);
        mma_f16(acc[2], a0, a1, a2, a3, w1.x, w1.y);
        mma_f16(acc[3], a0, a1, a2, a3, w1.z, w1.w);
    }
    #pragma unroll
    for (int nt = 0; nt < 4; nt++) {
        int col = n0 + nt * 8 + q * 2;
        sRes[(m0 + g)     * 68 + col]     += acc[nt][0];
        sRes[(m0 + g)     * 68 + col + 1] += acc[nt][1];
        sRes[(m0 + g + 8) * 68 + col]     += acc[nt][2];
        sRes[(m0 + g + 8) * 68 + col + 1] += acc[nt][3];
    }
    __syncthreads();

    // ---- Phase B2: z = lrelu(sRes + cvec); softmax; store fp16 scratch ----
    float2 zs[8];
    #pragma unroll
    for (int i = 0; i < 8; i++) {
        int e = ebase + i;
        bool v = (e0g + e) < E;
        float2 tv = *(const float2*)&sRes[e * 68 + c];
        float zx = lrelu_f(tv.x + cv2.x);
        float zy = lrelu_f(tv.y + cv2.y);
        zs[i] = v ? make_float2(zx, zy) : make_float2(-1e30f, -1e30f);
    }
    float2 ml = make_float2(-1e30f, -1e30f);
    #pragma unroll
    for (int i = 0; i < 8; i++) {
        ml.x = fmaxf(ml.x, zs[i].x);
        ml.y = fmaxf(ml.y, zs[i].y);
    }
    *(float2*)&sPM[warp * 68 + c] = ml;
    __syncthreads();
    float2 mb = make_float2(-1e30f, -1e30f);
    #pragma unroll
    for (int w2 = 0; w2 < 8; w2++) {
        mb.x = fmaxf(mb.x, sPM[w2 * 68 + c]);
        mb.y = fmaxf(mb.y, sPM[w2 * 68 + c + 1]);
    }
    float2 sl = make_float2(0.f, 0.f);
    #pragma unroll
    for (int i = 0; i < 8; i++) {
        int e = ebase + i;
        if ((e0g + e) < E) {
            float ex = __expf(zs[i].x - mb.x);
            float ey = __expf(zs[i].y - mb.y);
            sl.x += ex; sl.y += ey;
            float2 u = *(const float2*)&sUf[e * 64 + c];
            __half2 oh = __floats2half2_rn(u.x * ex, u.y * ey);
            __stcs(&g_scr[(size_t)(e0g + e) * 32 + lane], *(unsigned*)&oh);
        }
    }
    *(float2*)&sPS[warp * 68 + c] = sl;
    __syncthreads();
    if (warp == 0) {
        float sx = 0.f, sy = 0.f;
        #pragma unroll
        for (int w2 = 0; w2 < 8; w2++) {
            sx += sPS[w2 * 68 + c];
            sy += sPS[w2 * 68 + c + 1];
        }
        g_partM[c * MAXNB + blockIdx.x]       = mb.x;
        g_partM[(c + 1) * MAXNB + blockIdx.x] = mb.y;
        g_partS[c * MAXNB + blockIdx.x]       = sx;
        g_partS[(c + 1) * MAXNB + blockIdx.x] = sy;
    }
}

__global__ void k_combine(int NB)
{
    int c = blockIdx.x, t = threadIdx.x;
    float m = -1e30f, s = 0.f;
    for (int b = t; b < NB; b += 256) {
        float mb = g_partM[c * MAXNB + b], sb = g_partS[c * MAXNB + b];
        float M2 = fmaxf(m, mb);
        s = s * __expf(m - M2) + sb * __expf(mb - M2);
        m = M2;
    }
    __shared__ float sm[256], ss[256];
    sm[t] = m; ss[t] = s; __syncthreads();
    for (int off = 128; off > 0; off >>= 1) {
        if (t < off) {
            float M2 = fmaxf(sm[t], sm[t + off]);
            ss[t] = ss[t] * __expf(sm[t] - M2) + ss[t + off] * __expf(sm[t + off] - M2);
            sm[t] = M2;
        }
        __syncthreads();
    }
    if (t == 0) { g_Mg[c] = sm[0]; g_invS[c] = 1.f / ss[0]; }
}

__global__ void k_fact(int NB)
{
    int idx = blockIdx.x * 256 + threadIdx.x;
    int b = idx >> 6, c = idx & 63;
    if (b >= NB) return;
    g_factB[(size_t)b * 64 + c] = __expf(g_partM[c * MAXNB + b] - g_Mg[c]) * g_invS[c];
}

// final: out[i] (float4) = scr2[i] (uint2 fp16x4) * factors — 1 LDG.64 + 1 STG.128 per i
__global__ __launch_bounds__(256) void k_pass2(float4* __restrict__ out, int E)
{
    __shared__ float sf[64];
    int b = blockIdx.x;
    int t = threadIdx.x;
    if (t < 64) sf[t] = g_factB[(size_t)b * 64 + t];
    __syncthreads();
    const uint2* scr2 = (const uint2*)g_scr;
    size_t base = (size_t)b * 1024;
    #pragma unroll
    for (int r = 0; r < 4; r++) {
        size_t i = base + r * 256 + t;
        int e = (int)(i >> 4);
        if (e < E) {
            int c0 = ((int)i & 15) * 4;
            uint2 s = __ldcs(&scr2[i]);
            float2 v0 = __half22float2(*(__half2*)&s.x);
            float2 v1 = __half22float2(*(__half2*)&s.y);
            __stcs(&out[i], make_float4(v0.x * sf[c0], v0.y * sf[c0 + 1],
                                        v1.x * sf[c0 + 2], v1.y * sf[c0 + 3]));
        }
    }
}

extern "C" void kernel_launch(void* const* d_in, const int* in_sizes, int n_in,
                              void* d_out, int out_size)
{
    const float* eemb = (const float*)d_in[0];
    const float* ne   = (const float*)d_in[2];
    const float* Wa   = (const float*)d_in[3];
    const float* ba   = (const float*)d_in[4];
    const float* Wu   = (const float*)d_in[5];
    const float* bu   = (const float*)d_in[6];
    const float* We   = (const float*)d_in[7];
    const float* be   = (const float*)d_in[8];
    const float* Wn   = (const float*)d_in[9];
    const float* bn   = (const float*)d_in[10];
    const void*  eidx = d_in[11];
    float* out = (float*)d_out;

    int E = in_sizes[0] / 64;
    int N = in_sizes[2] / 64;
    int NB = (E + 63) / 64;

    cudaFuncSetAttribute(k_edge, cudaFuncAttributeMaxDynamicSharedMemorySize, SMEM_BYTES);

    k_prep<<<81, 256>>>(Wa, ba, Wu, bu, We, be, Wn, bn, (const unsigned*)eidx);
    k_node<<<(N + 31) / 32, 256>>>(ne, N);
    k_mark<<<1, 64>>>();
    k_edge<<<NB, 256, SMEM_BYTES>>>(eemb, eidx, bu, E);
    k_combine<<<64, 256>>>(NB);
    k_fact<<<(NB * 64 + 255) / 256, 256>>>(NB);
    k_pass2<<<NB, 256>>>((float4*)out, E);
}